// round 1
// baseline (speedup 1.0000x reference)
#include <cuda_runtime.h>
#include <cuda_bf16.h>

// Problem constants (hardcoded per reference: B=2, S=1024, H=32, KVH=8, HD=128, DM=4096)
#define T_TOK   2048
#define DMODEL  4096
#define QKVC    6144        // (32 + 2*8) * 128
#define NH      32
#define NKV     8
#define HDIM    128
#define SEQ     1024
#define NBATCH  2
#define QSCALE  0.08838834764831845f  // 1/sqrt(128)

// Scratch for the QKV projection result (RoPE applied in-place).
__device__ float g_qkv[(size_t)T_TOK * QKVC];

// ---------------------------------------------------------------------------
// Kernel 1: QKV GEMM  C[2048,6144] = A[2048,4096] * W[4096,6144]  (fp32)
// 128x128 tile, BK=16, 256 threads, 8x8 microtile per thread.
// ---------------------------------------------------------------------------
#define BM 128
#define BN 128
#define BK 16

__global__ __launch_bounds__(256) void gemm_kernel(const float* __restrict__ A,
                                                   const float* __restrict__ W) {
    __shared__ float As[BK][BM + 4];   // transposed A tile, padded
    __shared__ float Bs[BK][BN];

    const int tid = threadIdx.x;
    const int tx = tid & 15;          // 0..15 -> N
    const int ty = tid >> 4;          // 0..15 -> M
    const int rowBase = blockIdx.y * BM;
    const int colBase = blockIdx.x * BN;

    const float* Ab = A + (size_t)rowBase * DMODEL;
    const float* Bb = W + colBase;
    float* C = g_qkv + (size_t)rowBase * QKVC + colBase;

    float acc[8][8];
#pragma unroll
    for (int i = 0; i < 8; i++)
#pragma unroll
        for (int j = 0; j < 8; j++) acc[i][j] = 0.f;

    for (int k0 = 0; k0 < DMODEL; k0 += BK) {
        // Load A tile 128x16 (transposed into As[k][m])
#pragma unroll
        for (int i = 0; i < 2; i++) {
            int idx = tid + i * 256;
            int r  = idx >> 2;            // 0..127
            int c4 = (idx & 3) << 2;      // 0,4,8,12
            float4 a = *reinterpret_cast<const float4*>(Ab + (size_t)r * DMODEL + k0 + c4);
            As[c4 + 0][r] = a.x;
            As[c4 + 1][r] = a.y;
            As[c4 + 2][r] = a.z;
            As[c4 + 3][r] = a.w;
        }
        // Load B tile 16x128
#pragma unroll
        for (int i = 0; i < 2; i++) {
            int idx = tid + i * 256;
            int r  = idx >> 5;            // 0..15
            int c4 = (idx & 31) << 2;     // 0..124
            *reinterpret_cast<float4*>(&Bs[r][c4]) =
                *reinterpret_cast<const float4*>(Bb + (size_t)(k0 + r) * QKVC + c4);
        }
        __syncthreads();

#pragma unroll
        for (int k = 0; k < BK; k++) {
            float4 a0 = *reinterpret_cast<const float4*>(&As[k][ty * 8]);
            float4 a1 = *reinterpret_cast<const float4*>(&As[k][ty * 8 + 4]);
            float4 b0 = *reinterpret_cast<const float4*>(&Bs[k][tx * 8]);
            float4 b1 = *reinterpret_cast<const float4*>(&Bs[k][tx * 8 + 4]);
            float av[8] = {a0.x, a0.y, a0.z, a0.w, a1.x, a1.y, a1.z, a1.w};
            float bv[8] = {b0.x, b0.y, b0.z, b0.w, b1.x, b1.y, b1.z, b1.w};
#pragma unroll
            for (int i = 0; i < 8; i++)
#pragma unroll
                for (int j = 0; j < 8; j++) acc[i][j] = fmaf(av[i], bv[j], acc[i][j]);
        }
        __syncthreads();
    }

#pragma unroll
    for (int i = 0; i < 8; i++) {
        float* Crow = C + (size_t)(ty * 8 + i) * QKVC + tx * 8;
        float4 v0 = {acc[i][0], acc[i][1], acc[i][2], acc[i][3]};
        float4 v1 = {acc[i][4], acc[i][5], acc[i][6], acc[i][7]};
        *reinterpret_cast<float4*>(Crow)     = v0;
        *reinterpret_cast<float4*>(Crow + 4) = v1;
    }
}

// ---------------------------------------------------------------------------
// Kernel 2: RoPE in-place on q (heads 0..31, scaled by 1/sqrt(HD)) and k
// (heads 32..39). One thread per (token, head, pair).
// ---------------------------------------------------------------------------
__global__ __launch_bounds__(256) void rope_kernel(const float* __restrict__ cosT,
                                                   const float* __restrict__ sinT) {
    int idx = blockIdx.x * 256 + threadIdx.x;   // T_TOK * 40 * 64
    int d    = idx & 63;
    int head = (idx >> 6) % 40;
    int t    = idx / (64 * 40);

    float c = cosT[t * HDIM + d];   // cos[d] == cos[d+64] (concat layout)
    float s = sinT[t * HDIM + d];

    float* p = g_qkv + (size_t)t * QKVC + head * HDIM;
    float x1 = p[d];
    float x2 = p[d + 64];
    float o1 = x1 * c - x2 * s;
    float o2 = x2 * c + x1 * s;
    if (head < NH) { o1 *= QSCALE; o2 *= QSCALE; }   // fold softmax scale into q
    p[d]      = o1;
    p[d + 64] = o2;
}

// ---------------------------------------------------------------------------
// Kernel 3: flash attention (causal, GQA n_rep=4), fp32.
// Grid: (S/64, B*H). 256 threads: 16x16 -> 4x4 S microtile, 4x8 O microtile.
// K tile stored with XOR swizzle on 16B column-groups keyed by (row>>2) so
// S-phase K reads (8 phase-threads hitting rows 4*tx+j) are conflict-free.
// ---------------------------------------------------------------------------
#define ATTN_SMEM (3 * 64 * 128 * 4 + 64 * 65 * 4)

__global__ __launch_bounds__(256, 1) void attn_kernel(float* __restrict__ out) {
    extern __shared__ float sm[];
    float* Qs = sm;                    // [64][128]
    float* Ks = sm + 64 * 128;         // [64][128] swizzled
    float* Vs = sm + 2 * 64 * 128;     // [64][128]
    float* Ps = sm + 3 * 64 * 128;     // [64][65]

    const int tid = threadIdx.x;
    const int tx = tid & 15;
    const int ty = tid >> 4;
    const int xs = tx & 7;             // swizzle key for this thread's K rows

    const int bh  = blockIdx.y;
    const int b   = bh >> 5;
    const int h   = bh & 31;
    const int kvh = h >> 2;            // n_rep = 4
    const int q0  = blockIdx.x * 64;

    const float* Qg = g_qkv + (size_t)(b * SEQ + q0) * QKVC + h * HDIM;
    const float* Kg = g_qkv + (size_t)(b * SEQ) * QKVC + NH * HDIM + kvh * HDIM;
    const float* Vg = Kg + NKV * HDIM;

    // Load Q tile (64x128): plain layout.
#pragma unroll
    for (int i = 0; i < 8; i++) {
        int idx = tid + i * 256;
        int r = idx >> 5;
        int c = (idx & 31) << 2;
        *reinterpret_cast<float4*>(&Qs[r * 128 + c]) =
            *reinterpret_cast<const float4*>(Qg + (size_t)r * QKVC + c);
    }

    float m[4], l[4], o[4][8];
#pragma unroll
    for (int i = 0; i < 4; i++) {
        m[i] = -1e30f; l[i] = 0.f;
#pragma unroll
        for (int j = 0; j < 8; j++) o[i][j] = 0.f;
    }

    const int kb_end = blockIdx.x;     // inclusive (causal)
    for (int kb = 0; kb <= kb_end; kb++) {
        __syncthreads();               // protect Vs/Ks from previous iteration
        // Load K (swizzled) and V tiles.
#pragma unroll
        for (int i = 0; i < 8; i++) {
            int idx = tid + i * 256;
            int r  = idx >> 5;
            int cg = idx & 31;         // 16B column group
            float4 kv = *reinterpret_cast<const float4*>(Kg + (size_t)(kb * 64 + r) * QKVC + (cg << 2));
            float4 vv = *reinterpret_cast<const float4*>(Vg + (size_t)(kb * 64 + r) * QKVC + (cg << 2));
            int scg = cg ^ ((r >> 2) & 7);
            *reinterpret_cast<float4*>(&Ks[r * 128 + (scg << 2)]) = kv;
            *reinterpret_cast<float4*>(&Vs[r * 128 + (cg << 2)])  = vv;
        }
        __syncthreads();

        // S = Q K^T (4x4 microtile). Scale already folded into Q.
        float s4[4][4];
#pragma unroll
        for (int i = 0; i < 4; i++)
#pragma unroll
            for (int j = 0; j < 4; j++) s4[i][j] = 0.f;

#pragma unroll 4
        for (int d = 0; d < 128; d += 4) {
            int scol = (((d >> 2) ^ xs) << 2);
            float4 qv[4], kv[4];
#pragma unroll
            for (int i = 0; i < 4; i++)
                qv[i] = *reinterpret_cast<const float4*>(&Qs[(ty * 4 + i) * 128 + d]);
#pragma unroll
            for (int j = 0; j < 4; j++)
                kv[j] = *reinterpret_cast<const float4*>(&Ks[(tx * 4 + j) * 128 + scol]);
#pragma unroll
            for (int i = 0; i < 4; i++)
#pragma unroll
                for (int j = 0; j < 4; j++) {
                    s4[i][j] = fmaf(qv[i].x, kv[j].x, s4[i][j]);
                    s4[i][j] = fmaf(qv[i].y, kv[j].y, s4[i][j]);
                    s4[i][j] = fmaf(qv[i].z, kv[j].z, s4[i][j]);
                    s4[i][j] = fmaf(qv[i].w, kv[j].w, s4[i][j]);
                }
        }

        // Causal mask on the diagonal block only.
        if (kb == kb_end) {
#pragma unroll
            for (int i = 0; i < 4; i++)
#pragma unroll
                for (int j = 0; j < 4; j++)
                    if (kb * 64 + tx * 4 + j > q0 + ty * 4 + i) s4[i][j] = -1e30f;
        }

        // Online softmax: row reductions across the 16 threads sharing ty.
#pragma unroll
        for (int i = 0; i < 4; i++) {
            float rmax = fmaxf(fmaxf(s4[i][0], s4[i][1]), fmaxf(s4[i][2], s4[i][3]));
#pragma unroll
            for (int off = 1; off < 16; off <<= 1)
                rmax = fmaxf(rmax, __shfl_xor_sync(0xffffffffu, rmax, off));
            float nm   = fmaxf(m[i], rmax);
            float corr = __expf(m[i] - nm);
            float rs = 0.f;
#pragma unroll
            for (int j = 0; j < 4; j++) {
                s4[i][j] = __expf(s4[i][j] - nm);
                rs += s4[i][j];
            }
#pragma unroll
            for (int off = 1; off < 16; off <<= 1)
                rs += __shfl_xor_sync(0xffffffffu, rs, off);
            m[i] = nm;
            l[i] = l[i] * corr + rs;
#pragma unroll
            for (int j = 0; j < 8; j++) o[i][j] *= corr;
#pragma unroll
            for (int j = 0; j < 4; j++) Ps[(ty * 4 + i) * 65 + tx * 4 + j] = s4[i][j];
        }
        __syncthreads();

        // O += P @ V (rows ty*4.., cols tx*8..)
#pragma unroll 4
        for (int k = 0; k < 64; k++) {
            float4 v0 = *reinterpret_cast<const float4*>(&Vs[k * 128 + tx * 8]);
            float4 v1 = *reinterpret_cast<const float4*>(&Vs[k * 128 + tx * 8 + 4]);
#pragma unroll
            for (int i = 0; i < 4; i++) {
                float p = Ps[(ty * 4 + i) * 65 + k];
                o[i][0] = fmaf(p, v0.x, o[i][0]);
                o[i][1] = fmaf(p, v0.y, o[i][1]);
                o[i][2] = fmaf(p, v0.z, o[i][2]);
                o[i][3] = fmaf(p, v0.w, o[i][3]);
                o[i][4] = fmaf(p, v1.x, o[i][4]);
                o[i][5] = fmaf(p, v1.y, o[i][5]);
                o[i][6] = fmaf(p, v1.z, o[i][6]);
                o[i][7] = fmaf(p, v1.w, o[i][7]);
            }
        }
    }

    // Normalize and write: out[t, h*128 + c], t = b*S + q0 + row.
#pragma unroll
    for (int i = 0; i < 4; i++) {
        int t = b * SEQ + q0 + ty * 4 + i;
        float inv = 1.f / l[i];
        float* orow = out + (size_t)t * (NH * HDIM) + h * HDIM + tx * 8;
        float4 v0 = {o[i][0] * inv, o[i][1] * inv, o[i][2] * inv, o[i][3] * inv};
        float4 v1 = {o[i][4] * inv, o[i][5] * inv, o[i][6] * inv, o[i][7] * inv};
        *reinterpret_cast<float4*>(orow)     = v0;
        *reinterpret_cast<float4*>(orow + 4) = v1;
    }
}

// ---------------------------------------------------------------------------
extern "C" void kernel_launch(void* const* d_in, const int* in_sizes, int n_in,
                              void* d_out, int out_size) {
    const float* hidden = (const float*)d_in[0];
    const float* w_qkv  = (const float*)d_in[1];
    const float* cosT   = (const float*)d_in[2];
    const float* sinT   = (const float*)d_in[3];
    float* out = (float*)d_out;

    cudaFuncSetAttribute(attn_kernel, cudaFuncAttributeMaxDynamicSharedMemorySize, ATTN_SMEM);

    dim3 ggrid(QKVC / BN, T_TOK / BM);   // (48, 16)
    gemm_kernel<<<ggrid, 256>>>(hidden, w_qkv);

    int rope_threads = T_TOK * (NH + NKV) * 64;   // 5,242,880
    rope_kernel<<<rope_threads / 256, 256>>>(cosT, sinT);

    dim3 agrid(SEQ / 64, NBATCH * NH);   // (16, 64)
    attn_kernel<<<agrid, 256, ATTN_SMEM>>>(out);
}

// round 2
// speedup vs baseline: 1.8301x; 1.8301x over previous
#include <cuda_runtime.h>
#include <cuda_bf16.h>
#include <cstdint>

// Problem constants (B=2, S=1024, H=32, KVH=8, HD=128, DM=4096)
#define T_TOK   2048
#define DMODEL  4096
#define QKVC    6144
#define NH      32
#define NKV     8
#define HDIM    128
#define SEQ     1024
#define NBATCH  2
#define QSCALE  0.08838834764831845f

__device__ float g_qkv[(size_t)T_TOK * QKVC];

// ---------------------------------------------------------------------------
// Kernel 1: QKV GEMM via tf32 tensor cores.
// C[2048,6144] = A[2048,4096] @ W[4096,6144], fp32 I/O, tf32 mma m16n8k8.
// Block tile 128x128, BK=16, 256 threads (8 warps as 2x4), warp tile 64x32.
// Double-buffered smem; cvt.rna.tf32 applied at smem-store time.
// ---------------------------------------------------------------------------
#define BK 16
#define AS_STRIDE 20    // 16 + 4 pad  -> a-frag loads conflict-free
#define BS_STRIDE 136   // 128 + 8 pad -> b-frag loads conflict-free

__device__ __forceinline__ uint32_t f2tf32(float x) {
    uint32_t u;
    asm("cvt.rna.tf32.f32 %0, %1;" : "=r"(u) : "f"(x));
    return u;
}

#define MMA_TF32(d, a, b)                                                     \
    asm volatile(                                                             \
        "mma.sync.aligned.m16n8k8.row.col.f32.tf32.tf32.f32 "                 \
        "{%0,%1,%2,%3},{%4,%5,%6,%7},{%8,%9},{%0,%1,%2,%3};"                  \
        : "+f"(d[0]), "+f"(d[1]), "+f"(d[2]), "+f"(d[3])                      \
        : "r"(a[0]), "r"(a[1]), "r"(a[2]), "r"(a[3]), "r"(b[0]), "r"(b[1]))

__global__ __launch_bounds__(256) void gemm_tf32_kernel(const float* __restrict__ A,
                                                        const float* __restrict__ W) {
    __shared__ uint32_t As[2][128 * AS_STRIDE];
    __shared__ uint32_t Bs[2][BK * BS_STRIDE];

    const int tid  = threadIdx.x;
    const int wid  = tid >> 5;
    const int lane = tid & 31;
    const int gid  = lane >> 2;       // groupID 0..7
    const int tig  = lane & 3;        // thread-in-group 0..3
    const int wm   = wid >> 2;        // 0..1 (M)
    const int wn   = wid & 3;         // 0..3 (N)

    const int rowBase = blockIdx.y * 128;
    const int colBase = blockIdx.x * 128;

    // Global-load addressing (per thread):
    const int arow = tid >> 1;              // 0..127
    const int acol = (tid & 1) * 8;         // 0 or 8
    const int brow = tid >> 4;              // 0..15
    const int bcol = (tid & 15) * 8;        // 0..120

    const float* Ag = A + (size_t)(rowBase + arow) * DMODEL + acol;
    const float* Wg = W + (size_t)brow * QKVC + colBase + bcol;

    float acc[4][4][4];
#pragma unroll
    for (int i = 0; i < 4; i++)
#pragma unroll
        for (int j = 0; j < 4; j++)
#pragma unroll
            for (int c = 0; c < 4; c++) acc[i][j][c] = 0.f;

    // Preload tile 0
    float4 aPre0 = *reinterpret_cast<const float4*>(Ag);
    float4 aPre1 = *reinterpret_cast<const float4*>(Ag + 4);
    float4 bPre0 = *reinterpret_cast<const float4*>(Wg);
    float4 bPre1 = *reinterpret_cast<const float4*>(Wg + 4);

    {
        uint32_t* a = &As[0][arow * AS_STRIDE + acol];
        a[0] = f2tf32(aPre0.x); a[1] = f2tf32(aPre0.y); a[2] = f2tf32(aPre0.z); a[3] = f2tf32(aPre0.w);
        a[4] = f2tf32(aPre1.x); a[5] = f2tf32(aPre1.y); a[6] = f2tf32(aPre1.z); a[7] = f2tf32(aPre1.w);
        uint32_t* bp = &Bs[0][brow * BS_STRIDE + bcol];
        bp[0] = f2tf32(bPre0.x); bp[1] = f2tf32(bPre0.y); bp[2] = f2tf32(bPre0.z); bp[3] = f2tf32(bPre0.w);
        bp[4] = f2tf32(bPre1.x); bp[5] = f2tf32(bPre1.y); bp[6] = f2tf32(bPre1.z); bp[7] = f2tf32(bPre1.w);
    }
    __syncthreads();

    const int NTILES = DMODEL / BK;   // 256
    for (int kt = 0; kt < NTILES; kt++) {
        const int cur = kt & 1;
        const int nxt = cur ^ 1;

        // Prefetch next tile from global into registers.
        if (kt + 1 < NTILES) {
            const float* Agn = Ag + (kt + 1) * BK;
            const float* Wgn = Wg + (size_t)(kt + 1) * BK * QKVC;
            aPre0 = *reinterpret_cast<const float4*>(Agn);
            aPre1 = *reinterpret_cast<const float4*>(Agn + 4);
            bPre0 = *reinterpret_cast<const float4*>(Wgn);
            bPre1 = *reinterpret_cast<const float4*>(Wgn + 4);
        }

        // Compute on current buffer: 2 k-steps of 8.
        const uint32_t* Asb = As[cur];
        const uint32_t* Bsb = Bs[cur];
#pragma unroll
        for (int ks = 0; ks < BK; ks += 8) {
            uint32_t af[4][4], bf[4][2];
#pragma unroll
            for (int i = 0; i < 4; i++) {
                int r = wm * 64 + i * 16 + gid;
                af[i][0] = Asb[(r)     * AS_STRIDE + ks + tig];
                af[i][1] = Asb[(r + 8) * AS_STRIDE + ks + tig];
                af[i][2] = Asb[(r)     * AS_STRIDE + ks + tig + 4];
                af[i][3] = Asb[(r + 8) * AS_STRIDE + ks + tig + 4];
            }
#pragma unroll
            for (int j = 0; j < 4; j++) {
                int c = wn * 32 + j * 8 + gid;
                bf[j][0] = Bsb[(ks + tig)     * BS_STRIDE + c];
                bf[j][1] = Bsb[(ks + tig + 4) * BS_STRIDE + c];
            }
#pragma unroll
            for (int i = 0; i < 4; i++)
#pragma unroll
                for (int j = 0; j < 4; j++) MMA_TF32(acc[i][j], af[i], bf[j]);
        }

        // Store prefetched tile into the other buffer.
        if (kt + 1 < NTILES) {
            uint32_t* a = &As[nxt][arow * AS_STRIDE + acol];
            a[0] = f2tf32(aPre0.x); a[1] = f2tf32(aPre0.y); a[2] = f2tf32(aPre0.z); a[3] = f2tf32(aPre0.w);
            a[4] = f2tf32(aPre1.x); a[5] = f2tf32(aPre1.y); a[6] = f2tf32(aPre1.z); a[7] = f2tf32(aPre1.w);
            uint32_t* bp = &Bs[nxt][brow * BS_STRIDE + bcol];
            bp[0] = f2tf32(bPre0.x); bp[1] = f2tf32(bPre0.y); bp[2] = f2tf32(bPre0.z); bp[3] = f2tf32(bPre0.w);
            bp[4] = f2tf32(bPre1.x); bp[5] = f2tf32(bPre1.y); bp[6] = f2tf32(bPre1.z); bp[7] = f2tf32(bPre1.w);
        }
        __syncthreads();
    }

    // Epilogue: write accumulators (fp32).
    float* C = g_qkv + (size_t)rowBase * QKVC + colBase;
#pragma unroll
    for (int i = 0; i < 4; i++) {
#pragma unroll
        for (int j = 0; j < 4; j++) {
            int r = wm * 64 + i * 16 + gid;
            int c = wn * 32 + j * 8 + 2 * tig;
            float2 v0 = {acc[i][j][0], acc[i][j][1]};
            float2 v1 = {acc[i][j][2], acc[i][j][3]};
            *reinterpret_cast<float2*>(C + (size_t)(r)     * QKVC + c) = v0;
            *reinterpret_cast<float2*>(C + (size_t)(r + 8) * QKVC + c) = v1;
        }
    }
}

// ---------------------------------------------------------------------------
// Kernel 2: RoPE in-place (q scaled by 1/sqrt(HD)).
// ---------------------------------------------------------------------------
__global__ __launch_bounds__(256) void rope_kernel(const float* __restrict__ cosT,
                                                   const float* __restrict__ sinT) {
    int idx = blockIdx.x * 256 + threadIdx.x;
    int d    = idx & 63;
    int head = (idx >> 6) % 40;
    int t    = idx / (64 * 40);

    float c = cosT[t * HDIM + d];
    float s = sinT[t * HDIM + d];

    float* p = g_qkv + (size_t)t * QKVC + head * HDIM;
    float x1 = p[d];
    float x2 = p[d + 64];
    float o1 = x1 * c - x2 * s;
    float o2 = x2 * c + x1 * s;
    if (head < NH) { o1 *= QSCALE; o2 *= QSCALE; }
    p[d]      = o1;
    p[d + 64] = o2;
}

// ---------------------------------------------------------------------------
// Kernel 3: flash attention (causal, GQA n_rep=4), fp32 (unchanged).
// ---------------------------------------------------------------------------
#define ATTN_SMEM (3 * 64 * 128 * 4 + 64 * 65 * 4)

__global__ __launch_bounds__(256, 1) void attn_kernel(float* __restrict__ out) {
    extern __shared__ float sm[];
    float* Qs = sm;
    float* Ks = sm + 64 * 128;
    float* Vs = sm + 2 * 64 * 128;
    float* Ps = sm + 3 * 64 * 128;

    const int tid = threadIdx.x;
    const int tx = tid & 15;
    const int ty = tid >> 4;
    const int xs = tx & 7;

    const int bh  = blockIdx.y;
    const int b   = bh >> 5;
    const int h   = bh & 31;
    const int kvh = h >> 2;
    const int q0  = blockIdx.x * 64;

    const float* Qg = g_qkv + (size_t)(b * SEQ + q0) * QKVC + h * HDIM;
    const float* Kg = g_qkv + (size_t)(b * SEQ) * QKVC + NH * HDIM + kvh * HDIM;
    const float* Vg = Kg + NKV * HDIM;

#pragma unroll
    for (int i = 0; i < 8; i++) {
        int idx = tid + i * 256;
        int r = idx >> 5;
        int c = (idx & 31) << 2;
        *reinterpret_cast<float4*>(&Qs[r * 128 + c]) =
            *reinterpret_cast<const float4*>(Qg + (size_t)r * QKVC + c);
    }

    float m[4], l[4], o[4][8];
#pragma unroll
    for (int i = 0; i < 4; i++) {
        m[i] = -1e30f; l[i] = 0.f;
#pragma unroll
        for (int j = 0; j < 8; j++) o[i][j] = 0.f;
    }

    const int kb_end = blockIdx.x;
    for (int kb = 0; kb <= kb_end; kb++) {
        __syncthreads();
#pragma unroll
        for (int i = 0; i < 8; i++) {
            int idx = tid + i * 256;
            int r  = idx >> 5;
            int cg = idx & 31;
            float4 kv = *reinterpret_cast<const float4*>(Kg + (size_t)(kb * 64 + r) * QKVC + (cg << 2));
            float4 vv = *reinterpret_cast<const float4*>(Vg + (size_t)(kb * 64 + r) * QKVC + (cg << 2));
            int scg = cg ^ ((r >> 2) & 7);
            *reinterpret_cast<float4*>(&Ks[r * 128 + (scg << 2)]) = kv;
            *reinterpret_cast<float4*>(&Vs[r * 128 + (cg << 2)])  = vv;
        }
        __syncthreads();

        float s4[4][4];
#pragma unroll
        for (int i = 0; i < 4; i++)
#pragma unroll
            for (int j = 0; j < 4; j++) s4[i][j] = 0.f;

#pragma unroll 4
        for (int d = 0; d < 128; d += 4) {
            int scol = (((d >> 2) ^ xs) << 2);
            float4 qv[4], kv[4];
#pragma unroll
            for (int i = 0; i < 4; i++)
                qv[i] = *reinterpret_cast<const float4*>(&Qs[(ty * 4 + i) * 128 + d]);
#pragma unroll
            for (int j = 0; j < 4; j++)
                kv[j] = *reinterpret_cast<const float4*>(&Ks[(tx * 4 + j) * 128 + scol]);
#pragma unroll
            for (int i = 0; i < 4; i++)
#pragma unroll
                for (int j = 0; j < 4; j++) {
                    s4[i][j] = fmaf(qv[i].x, kv[j].x, s4[i][j]);
                    s4[i][j] = fmaf(qv[i].y, kv[j].y, s4[i][j]);
                    s4[i][j] = fmaf(qv[i].z, kv[j].z, s4[i][j]);
                    s4[i][j] = fmaf(qv[i].w, kv[j].w, s4[i][j]);
                }
        }

        if (kb == kb_end) {
#pragma unroll
            for (int i = 0; i < 4; i++)
#pragma unroll
                for (int j = 0; j < 4; j++)
                    if (kb * 64 + tx * 4 + j > q0 + ty * 4 + i) s4[i][j] = -1e30f;
        }

#pragma unroll
        for (int i = 0; i < 4; i++) {
            float rmax = fmaxf(fmaxf(s4[i][0], s4[i][1]), fmaxf(s4[i][2], s4[i][3]));
#pragma unroll
            for (int off = 1; off < 16; off <<= 1)
                rmax = fmaxf(rmax, __shfl_xor_sync(0xffffffffu, rmax, off));
            float nm   = fmaxf(m[i], rmax);
            float corr = __expf(m[i] - nm);
            float rs = 0.f;
#pragma unroll
            for (int j = 0; j < 4; j++) {
                s4[i][j] = __expf(s4[i][j] - nm);
                rs += s4[i][j];
            }
#pragma unroll
            for (int off = 1; off < 16; off <<= 1)
                rs += __shfl_xor_sync(0xffffffffu, rs, off);
            m[i] = nm;
            l[i] = l[i] * corr + rs;
#pragma unroll
            for (int j = 0; j < 8; j++) o[i][j] *= corr;
#pragma unroll
            for (int j = 0; j < 4; j++) Ps[(ty * 4 + i) * 65 + tx * 4 + j] = s4[i][j];
        }
        __syncthreads();

#pragma unroll 4
        for (int k = 0; k < 64; k++) {
            float4 v0 = *reinterpret_cast<const float4*>(&Vs[k * 128 + tx * 8]);
            float4 v1 = *reinterpret_cast<const float4*>(&Vs[k * 128 + tx * 8 + 4]);
#pragma unroll
            for (int i = 0; i < 4; i++) {
                float p = Ps[(ty * 4 + i) * 65 + k];
                o[i][0] = fmaf(p, v0.x, o[i][0]);
                o[i][1] = fmaf(p, v0.y, o[i][1]);
                o[i][2] = fmaf(p, v0.z, o[i][2]);
                o[i][3] = fmaf(p, v0.w, o[i][3]);
                o[i][4] = fmaf(p, v1.x, o[i][4]);
                o[i][5] = fmaf(p, v1.y, o[i][5]);
                o[i][6] = fmaf(p, v1.z, o[i][6]);
                o[i][7] = fmaf(p, v1.w, o[i][7]);
            }
        }
    }

#pragma unroll
    for (int i = 0; i < 4; i++) {
        int t = b * SEQ + q0 + ty * 4 + i;
        float inv = 1.f / l[i];
        float* orow = out + (size_t)t * (NH * HDIM) + h * HDIM + tx * 8;
        float4 v0 = {o[i][0] * inv, o[i][1] * inv, o[i][2] * inv, o[i][3] * inv};
        float4 v1 = {o[i][4] * inv, o[i][5] * inv, o[i][6] * inv, o[i][7] * inv};
        *reinterpret_cast<float4*>(orow)     = v0;
        *reinterpret_cast<float4*>(orow + 4) = v1;
    }
}

// ---------------------------------------------------------------------------
extern "C" void kernel_launch(void* const* d_in, const int* in_sizes, int n_in,
                              void* d_out, int out_size) {
    const float* hidden = (const float*)d_in[0];
    const float* w_qkv  = (const float*)d_in[1];
    const float* cosT   = (const float*)d_in[2];
    const float* sinT   = (const float*)d_in[3];
    float* out = (float*)d_out;

    cudaFuncSetAttribute(attn_kernel, cudaFuncAttributeMaxDynamicSharedMemorySize, ATTN_SMEM);

    dim3 ggrid(QKVC / 128, T_TOK / 128);   // (48, 16)
    gemm_tf32_kernel<<<ggrid, 256>>>(hidden, w_qkv);

    int rope_threads = T_TOK * (NH + NKV) * 64;
    rope_kernel<<<rope_threads / 256, 256>>>(cosT, sinT);

    dim3 agrid(SEQ / 64, NBATCH * NH);     // (16, 64)
    attn_kernel<<<agrid, 256, ATTN_SMEM>>>(out);
}

// round 4
// speedup vs baseline: 2.0181x; 1.1027x over previous
#include <cuda_runtime.h>
#include <cuda_bf16.h>
#include <cstdint>

// Problem constants (B=2, S=1024, H=32, KVH=8, HD=128, DM=4096)
#define T_TOK   2048
#define DMODEL  4096
#define QKVC    6144
#define NH      32
#define NKV     8
#define HDIM    128
#define SEQ     1024
#define NBATCH  2
#define QSCALE  0.08838834764831845f

__device__ float g_qkv[(size_t)T_TOK * QKVC];

__device__ __forceinline__ uint32_t f2tf32(float x) {
    uint32_t u;
    asm("cvt.rna.tf32.f32 %0, %1;" : "=r"(u) : "f"(x));
    return u;
}

#define MMA_TF32(d, a, b)                                                     \
    asm volatile(                                                             \
        "mma.sync.aligned.m16n8k8.row.col.f32.tf32.tf32.f32 "                 \
        "{%0,%1,%2,%3},{%4,%5,%6,%7},{%8,%9},{%0,%1,%2,%3};"                  \
        : "+f"(d[0]), "+f"(d[1]), "+f"(d[2]), "+f"(d[3])                      \
        : "r"(a[0]), "r"(a[1]), "r"(a[2]), "r"(a[3]), "r"(b[0]), "r"(b[1]))

// ---------------------------------------------------------------------------
// Kernel 1: QKV GEMM via tf32 mma.sync with FRAGMENT-MAJOR smem layout.
// C[2048,6144] = A[2048,4096] @ W[4096,6144].
// Block 128x128, BK=16, 256 threads (8 warps 2x4), warp tile 64x32.
//
// A smem: word addr = (ks*8 + rowblk)*128 + lane*4 + reg
//   element (r16, kc): lane=(r16%8)*4 + kc%4, reg=(kc>=4)*2 + (r16>=8)
//   -> a-fragment load is one LDS.128 per 16-row block (conflict-free).
// B smem: word addr = (ks*16 + nblk)*66 + lane*2 + reg   (66 = 64 + 2 pad)
//   element (kc, nn): lane=nn*4 + kc%4, reg=(kc>=4)
//   -> b-fragment load is one LDS.64 per 8-col block (conflict-free).
// ---------------------------------------------------------------------------
__global__ __launch_bounds__(256) void gemm_tf32_kernel(const float* __restrict__ A,
                                                        const float* __restrict__ W) {
    __shared__ uint32_t As[2][2048];   // 2 ksteps * 8 rowblks * 128
    __shared__ uint32_t Bs[2][2112];   // 2 ksteps * 16 nblks * 66

    const int tid  = threadIdx.x;
    const int wid  = tid >> 5;
    const int lane = tid & 31;
    const int gid  = lane >> 2;
    const int tig  = lane & 3;
    const int wm   = wid >> 2;        // 0..1
    const int wn   = wid & 3;         // 0..3

    const int rowBase = blockIdx.y * 128;
    const int colBase = blockIdx.x * 128;

    // --- staging decode (2 quads each for A and B per tile) ---
    // A quad q = tid + 256*it: row=q>>2, ks=(q>>1)&1, kh=q&1
    int aRow[2], aKs[2], aKh[2];
    int bK[2], bNq[2];
#pragma unroll
    for (int it = 0; it < 2; it++) {
        int q = tid + (it << 8);
        aRow[it] = q >> 2; aKs[it] = (q >> 1) & 1; aKh[it] = q & 1;
        bK[it] = q >> 5;   bNq[it] = q & 31;
    }

    float acc[4][4][4];
#pragma unroll
    for (int i = 0; i < 4; i++)
#pragma unroll
        for (int j = 0; j < 4; j++)
#pragma unroll
            for (int c = 0; c < 4; c++) acc[i][j][c] = 0.f;

    float4 aPre[2], bPre[2];

    // ---- global load of tile kt into registers ----
#define LOAD_TILE(kt)                                                          \
    do {                                                                       \
        int k0 = (kt) * 16;                                                    \
        _Pragma("unroll")                                                      \
        for (int it = 0; it < 2; it++) {                                       \
            aPre[it] = *reinterpret_cast<const float4*>(                       \
                A + (size_t)(rowBase + aRow[it]) * DMODEL + k0 +               \
                aKs[it] * 8 + aKh[it] * 4);                                    \
            bPre[it] = *reinterpret_cast<const float4*>(                       \
                W + (size_t)(k0 + bK[it]) * QKVC + colBase + bNq[it] * 4);     \
        }                                                                      \
    } while (0)

    // ---- store registers into fragment-major smem buffer ----
#define STORE_TILE(buf)                                                        \
    do {                                                                       \
        _Pragma("unroll")                                                      \
        for (int it = 0; it < 2; it++) {                                       \
            int r16 = aRow[it] & 15, rb = aRow[it] >> 4;                       \
            int lane0 = (r16 & 7) << 2;                                        \
            int reg = (aKh[it] << 1) + (r16 >> 3);                             \
            uint32_t* dstA = &As[buf][((aKs[it] << 3) + rb) << 7];             \
            uint32_t ua[4] = { f2tf32(aPre[it].x), f2tf32(aPre[it].y),         \
                               f2tf32(aPre[it].z), f2tf32(aPre[it].w) };       \
            int rot = (r16 >> 1) & 3;                                          \
            _Pragma("unroll")                                                  \
            for (int i = 0; i < 4; i++) {                                      \
                int j = (i + rot) & 3;                                         \
                dstA[((lane0 + j) << 2) + reg] = ua[j];                        \
            }                                                                  \
            int kc = bK[it] & 7, ks = bK[it] >> 3;                             \
            int kl = kc & 3, rg = kc >> 2;                                     \
            int grp = (ks << 4) + (bNq[it] >> 1);                              \
            int nn0 = (bNq[it] & 1) << 2;                                      \
            uint32_t* dstB = &Bs[buf][grp * 66];                               \
            uint32_t ub[4] = { f2tf32(bPre[it].x), f2tf32(bPre[it].y),         \
                               f2tf32(bPre[it].z), f2tf32(bPre[it].w) };       \
            _Pragma("unroll")                                                  \
            for (int i = 0; i < 4; i++) {                                      \
                int nn = nn0 + i;                                              \
                dstB[(((nn << 2) + kl) << 1) + rg] = ub[i];                    \
            }                                                                  \
        }                                                                      \
    } while (0)

    LOAD_TILE(0);
    STORE_TILE(0);
    __syncthreads();

    const int NTILES = DMODEL / 16;   // 256
    for (int kt = 0; kt < NTILES; kt++) {
        const int cur = kt & 1;
        const int nxt = cur ^ 1;

        if (kt + 1 < NTILES) LOAD_TILE(kt + 1);

        // Compute on current buffer: 2 k8-steps.
#pragma unroll
        for (int ks = 0; ks < 2; ks++) {
            uint4 av[4];
            uint2 bv[4];
#pragma unroll
            for (int i = 0; i < 4; i++)
                av[i] = *reinterpret_cast<const uint4*>(
                    &As[cur][(((ks << 3) + (wm << 2) + i) << 7) + (lane << 2)]);
#pragma unroll
            for (int j = 0; j < 4; j++)
                bv[j] = *reinterpret_cast<const uint2*>(
                    &Bs[cur][((ks << 4) + (wn << 2) + j) * 66 + (lane << 1)]);
#pragma unroll
            for (int i = 0; i < 4; i++)
#pragma unroll
                for (int j = 0; j < 4; j++)
                    MMA_TF32(acc[i][j], (reinterpret_cast<uint32_t*>(&av[i])),
                             (reinterpret_cast<uint32_t*>(&bv[j])));
        }

        if (kt + 1 < NTILES) STORE_TILE(nxt);
        __syncthreads();
    }

    // Epilogue.
    float* C = g_qkv + (size_t)rowBase * QKVC + colBase;
#pragma unroll
    for (int i = 0; i < 4; i++) {
#pragma unroll
        for (int j = 0; j < 4; j++) {
            int r = wm * 64 + i * 16 + gid;
            int c = wn * 32 + j * 8 + 2 * tig;
            float2 v0 = {acc[i][j][0], acc[i][j][1]};
            float2 v1 = {acc[i][j][2], acc[i][j][3]};
            *reinterpret_cast<float2*>(C + (size_t)(r)     * QKVC + c) = v0;
            *reinterpret_cast<float2*>(C + (size_t)(r + 8) * QKVC + c) = v1;
        }
    }
}

// ---------------------------------------------------------------------------
// Kernel 2: RoPE in-place (q scaled by 1/sqrt(HD)).
// ---------------------------------------------------------------------------
__global__ __launch_bounds__(256) void rope_kernel(const float* __restrict__ cosT,
                                                   const float* __restrict__ sinT) {
    int idx = blockIdx.x * 256 + threadIdx.x;
    int d    = idx & 63;
    int head = (idx >> 6) % 40;
    int t    = idx / (64 * 40);

    float c = cosT[t * HDIM + d];
    float s = sinT[t * HDIM + d];

    float* p = g_qkv + (size_t)t * QKVC + head * HDIM;
    float x1 = p[d];
    float x2 = p[d + 64];
    float o1 = x1 * c - x2 * s;
    float o2 = x2 * c + x1 * s;
    if (head < NH) { o1 *= QSCALE; o2 *= QSCALE; }
    p[d]      = o1;
    p[d + 64] = o2;
}

// ---------------------------------------------------------------------------
// Kernel 3: flash attention (causal, GQA n_rep=4), fp32 (unchanged).
// ---------------------------------------------------------------------------
#define ATTN_SMEM (3 * 64 * 128 * 4 + 64 * 65 * 4)

__global__ __launch_bounds__(256, 1) void attn_kernel(float* __restrict__ out) {
    extern __shared__ float sm[];
    float* Qs = sm;
    float* Ks = sm + 64 * 128;
    float* Vs = sm + 2 * 64 * 128;
    float* Ps = sm + 3 * 64 * 128;

    const int tid = threadIdx.x;
    const int tx = tid & 15;
    const int ty = tid >> 4;
    const int xs = tx & 7;

    const int bh  = blockIdx.y;
    const int b   = bh >> 5;
    const int h   = bh & 31;
    const int kvh = h >> 2;
    const int q0  = blockIdx.x * 64;

    const float* Qg = g_qkv + (size_t)(b * SEQ + q0) * QKVC + h * HDIM;
    const float* Kg = g_qkv + (size_t)(b * SEQ) * QKVC + NH * HDIM + kvh * HDIM;
    const float* Vg = Kg + NKV * HDIM;

#pragma unroll
    for (int i = 0; i < 8; i++) {
        int idx = tid + i * 256;
        int r = idx >> 5;
        int c = (idx & 31) << 2;
        *reinterpret_cast<float4*>(&Qs[r * 128 + c]) =
            *reinterpret_cast<const float4*>(Qg + (size_t)r * QKVC + c);
    }

    float m[4], l[4], o[4][8];
#pragma unroll
    for (int i = 0; i < 4; i++) {
        m[i] = -1e30f; l[i] = 0.f;
#pragma unroll
        for (int j = 0; j < 8; j++) o[i][j] = 0.f;
    }

    const int kb_end = blockIdx.x;
    for (int kb = 0; kb <= kb_end; kb++) {
        __syncthreads();
#pragma unroll
        for (int i = 0; i < 8; i++) {
            int idx = tid + i * 256;
            int r  = idx >> 5;
            int cg = idx & 31;
            float4 kv = *reinterpret_cast<const float4*>(Kg + (size_t)(kb * 64 + r) * QKVC + (cg << 2));
            float4 vv = *reinterpret_cast<const float4*>(Vg + (size_t)(kb * 64 + r) * QKVC + (cg << 2));
            int scg = cg ^ ((r >> 2) & 7);
            *reinterpret_cast<float4*>(&Ks[r * 128 + (scg << 2)]) = kv;
            *reinterpret_cast<float4*>(&Vs[r * 128 + (cg << 2)])  = vv;
        }
        __syncthreads();

        float s4[4][4];
#pragma unroll
        for (int i = 0; i < 4; i++)
#pragma unroll
            for (int j = 0; j < 4; j++) s4[i][j] = 0.f;

#pragma unroll 4
        for (int d = 0; d < 128; d += 4) {
            int scol = (((d >> 2) ^ xs) << 2);
            float4 qv[4], kv[4];
#pragma unroll
            for (int i = 0; i < 4; i++)
                qv[i] = *reinterpret_cast<const float4*>(&Qs[(ty * 4 + i) * 128 + d]);
#pragma unroll
            for (int j = 0; j < 4; j++)
                kv[j] = *reinterpret_cast<const float4*>(&Ks[(tx * 4 + j) * 128 + scol]);
#pragma unroll
            for (int i = 0; i < 4; i++)
#pragma unroll
                for (int j = 0; j < 4; j++) {
                    s4[i][j] = fmaf(qv[i].x, kv[j].x, s4[i][j]);
                    s4[i][j] = fmaf(qv[i].y, kv[j].y, s4[i][j]);
                    s4[i][j] = fmaf(qv[i].z, kv[j].z, s4[i][j]);
                    s4[i][j] = fmaf(qv[i].w, kv[j].w, s4[i][j]);
                }
        }

        if (kb == kb_end) {
#pragma unroll
            for (int i = 0; i < 4; i++)
#pragma unroll
                for (int j = 0; j < 4; j++)
                    if (kb * 64 + tx * 4 + j > q0 + ty * 4 + i) s4[i][j] = -1e30f;
        }

#pragma unroll
        for (int i = 0; i < 4; i++) {
            float rmax = fmaxf(fmaxf(s4[i][0], s4[i][1]), fmaxf(s4[i][2], s4[i][3]));
#pragma unroll
            for (int off = 1; off < 16; off <<= 1)
                rmax = fmaxf(rmax, __shfl_xor_sync(0xffffffffu, rmax, off));
            float nm   = fmaxf(m[i], rmax);
            float corr = __expf(m[i] - nm);
            float rs = 0.f;
#pragma unroll
            for (int j = 0; j < 4; j++) {
                s4[i][j] = __expf(s4[i][j] - nm);
                rs += s4[i][j];
            }
#pragma unroll
            for (int off = 1; off < 16; off <<= 1)
                rs += __shfl_xor_sync(0xffffffffu, rs, off);
            m[i] = nm;
            l[i] = l[i] * corr + rs;
#pragma unroll
            for (int j = 0; j < 8; j++) o[i][j] *= corr;
#pragma unroll
            for (int j = 0; j < 4; j++) Ps[(ty * 4 + i) * 65 + tx * 4 + j] = s4[i][j];
        }
        __syncthreads();

#pragma unroll 4
        for (int k = 0; k < 64; k++) {
            float4 v0 = *reinterpret_cast<const float4*>(&Vs[k * 128 + tx * 8]);
            float4 v1 = *reinterpret_cast<const float4*>(&Vs[k * 128 + tx * 8 + 4]);
#pragma unroll
            for (int i = 0; i < 4; i++) {
                float p = Ps[(ty * 4 + i) * 65 + k];
                o[i][0] = fmaf(p, v0.x, o[i][0]);
                o[i][1] = fmaf(p, v0.y, o[i][1]);
                o[i][2] = fmaf(p, v0.z, o[i][2]);
                o[i][3] = fmaf(p, v0.w, o[i][3]);
                o[i][4] = fmaf(p, v1.x, o[i][4]);
                o[i][5] = fmaf(p, v1.y, o[i][5]);
                o[i][6] = fmaf(p, v1.z, o[i][6]);
                o[i][7] = fmaf(p, v1.w, o[i][7]);
            }
        }
    }

#pragma unroll
    for (int i = 0; i < 4; i++) {
        int t = b * SEQ + q0 + ty * 4 + i;
        float inv = 1.f / l[i];
        float* orow = out + (size_t)t * (NH * HDIM) + h * HDIM + tx * 8;
        float4 v0 = {o[i][0] * inv, o[i][1] * inv, o[i][2] * inv, o[i][3] * inv};
        float4 v1 = {o[i][4] * inv, o[i][5] * inv, o[i][6] * inv, o[i][7] * inv};
        *reinterpret_cast<float4*>(orow)     = v0;
        *reinterpret_cast<float4*>(orow + 4) = v1;
    }
}

// ---------------------------------------------------------------------------
extern "C" void kernel_launch(void* const* d_in, const int* in_sizes, int n_in,
                              void* d_out, int out_size) {
    const float* hidden = (const float*)d_in[0];
    const float* w_qkv  = (const float*)d_in[1];
    const float* cosT   = (const float*)d_in[2];
    const float* sinT   = (const float*)d_in[3];
    float* out = (float*)d_out;

    cudaFuncSetAttribute(attn_kernel, cudaFuncAttributeMaxDynamicSharedMemorySize, ATTN_SMEM);

    dim3 ggrid(QKVC / 128, T_TOK / 128);   // (48, 16)
    gemm_tf32_kernel<<<ggrid, 256>>>(hidden, w_qkv);

    int rope_threads = T_TOK * (NH + NKV) * 64;
    rope_kernel<<<rope_threads / 256, 256>>>(cosT, sinT);

    dim3 agrid(SEQ / 64, NBATCH * NH);     // (16, 64)
    attn_kernel<<<agrid, 256, ATTN_SMEM>>>(out);
}

// round 5
// speedup vs baseline: 2.2383x; 1.1091x over previous
#include <cuda_runtime.h>
#include <cuda_bf16.h>
#include <cstdint>

// Problem constants (B=2, S=1024, H=32, KVH=8, HD=128, DM=4096)
#define T_TOK   2048
#define DMODEL  4096
#define QKVC    6144
#define NH      32
#define NKV     8
#define HDIM    128
#define SEQ     1024
#define NBATCH  2
#define QSCALE  0.08838834764831845f

__device__ float g_qkv[(size_t)T_TOK * QKVC];
// Pre-packed tf32 operands in fragment-major tile layout (2048 words / 128x16 tile).
__device__ uint32_t g_pa[(size_t)T_TOK * DMODEL];   // [mTile][kTile][2048]
__device__ uint32_t g_pb[(size_t)QKVC * DMODEL];    // [nTile][kTile][2048]

__device__ __forceinline__ uint32_t f2tf32(float x) {
    uint32_t u;
    asm("cvt.rna.tf32.f32 %0, %1;" : "=r"(u) : "f"(x));
    return u;
}

#define MMA_TF32(d, a, b)                                                     \
    asm volatile(                                                             \
        "mma.sync.aligned.m16n8k8.row.col.f32.tf32.tf32.f32 "                 \
        "{%0,%1,%2,%3},{%4,%5,%6,%7},{%8,%9},{%0,%1,%2,%3};"                  \
        : "+f"(d[0]), "+f"(d[1]), "+f"(d[2]), "+f"(d[3])                      \
        : "r"(a[0]), "r"(a[1]), "r"(a[2]), "r"(a[3]), "r"(b[0]), "r"(b[1]))

__device__ __forceinline__ void cp_async16(uint32_t smem_addr, const void* gptr) {
    asm volatile("cp.async.cg.shared.global [%0], [%1], 16;"
                 :: "r"(smem_addr), "l"(gptr) : "memory");
}
#define CP_COMMIT() asm volatile("cp.async.commit_group;" ::: "memory")
#define CP_WAIT2()  asm volatile("cp.async.wait_group 2;" ::: "memory")

// ---------------------------------------------------------------------------
// Kernel 0a: pack A [2048,4096] fp32 -> g_pa tf32 fragment-major tiles.
// A-tile layout (per 128 rows x 16 k): word = (ks*8+rb)*128 + lane*4 + reg
//   lane = (r16&7)*4 + (kc&3); reg = (kc>=4)*2 + (r16>=8)
// ---------------------------------------------------------------------------
__global__ __launch_bounds__(256) void pack_a_kernel(const float* __restrict__ A) {
    int i = blockIdx.x * 256 + threadIdx.x;       // one float4 along k
    int r  = i >> 10;                             // 0..2047
    int k0 = (i & 1023) << 2;                     // 0..4092 step 4
    float4 v = *reinterpret_cast<const float4*>(A + (size_t)r * DMODEL + k0);

    int mTile = r >> 7, rLoc = r & 127;
    int kTile = k0 >> 4, kLoc = k0 & 15;          // 0,4,8,12
    uint32_t* dst = g_pa + ((size_t)(mTile * (DMODEL / 16) + kTile)) * 2048;

    int ks  = kLoc >> 3;
    int kc0 = kLoc & 7;                           // 0 or 4
    int rb  = rLoc >> 4, r16 = rLoc & 15;
    int reg = ((kc0 >= 4) ? 2 : 0) + ((r16 >= 8) ? 1 : 0);
    int base = ((ks << 3) + rb) << 7;
    int lane0 = (r16 & 7) << 2;
    float a[4] = {v.x, v.y, v.z, v.w};
#pragma unroll
    for (int j = 0; j < 4; j++)
        dst[base + ((lane0 + j) << 2) + reg] = f2tf32(a[j]);
}

// ---------------------------------------------------------------------------
// Kernel 0b: pack W [4096,6144] fp32 -> g_pb tf32 fragment-major tiles.
// B-tile layout (per 128 cols x 16 k): word = (ks*16+nblk)*64 + lane*2 + reg
//   lane = nn*4 + (kc&3); reg = (kc>=4)
// ---------------------------------------------------------------------------
__global__ __launch_bounds__(256) void pack_w_kernel(const float* __restrict__ W) {
    int i = blockIdx.x * 256 + threadIdx.x;       // one float4 along n
    int k  = i / 1536;
    int n0 = (i - k * 1536) << 2;
    float4 v = *reinterpret_cast<const float4*>(W + (size_t)k * QKVC + n0);

    int nTile = n0 >> 7, nLoc0 = n0 & 127;
    int kTile = k >> 4,  kLoc  = k & 15;
    uint32_t* dst = g_pb + ((size_t)(nTile * (DMODEL / 16) + kTile)) * 2048;

    int ks = kLoc >> 3, kc = kLoc & 7;
    int kl = kc & 3, rg = kc >> 2;
    float a[4] = {v.x, v.y, v.z, v.w};
#pragma unroll
    for (int j = 0; j < 4; j++) {
        int n = nLoc0 + j;
        int nblk = n >> 3, nn = n & 7;
        dst[((ks << 4) + nblk) * 64 + (((nn << 2) + kl) << 1) + rg] = f2tf32(a[j]);
    }
}

// ---------------------------------------------------------------------------
// Kernel 1: QKV GEMM, tf32 mma.sync, pre-packed operands, cp.async 4-stage.
// Block 128x128, BK=16, 256 threads (8 warps 2x4), warp tile 64x32.
// smem per stage: A 8KB + B 8KB; 4 stages = 64KB dynamic.
// ---------------------------------------------------------------------------
#define GSTAGES 4

__global__ __launch_bounds__(256, 2) void gemm_tf32_kernel() {
    extern __shared__ __align__(16) uint32_t smem[];   // 4 * 4096 words

    const int tid  = threadIdx.x;
    const int wid  = tid >> 5;
    const int lane = tid & 31;
    const int gid  = lane >> 2;
    const int tig  = lane & 3;
    const int wm   = wid >> 2;
    const int wn   = wid & 3;

    const uint32_t smem_base = (uint32_t)__cvta_generic_to_shared(smem);
    const uint32_t* pa = g_pa + (size_t)blockIdx.y * (DMODEL / 16) * 2048;
    const uint32_t* pb = g_pb + (size_t)blockIdx.x * (DMODEL / 16) * 2048;

    const int NTILES = DMODEL / 16;   // 256

    // Issue one tile's copies into stage s.
#define ISSUE(kt, s)                                                           \
    do {                                                                       \
        uint32_t sa = smem_base + (uint32_t)(s) * 16384;                       \
        const uint32_t* gA = pa + (size_t)(kt) * 2048 + tid * 4;               \
        const uint32_t* gB = pb + (size_t)(kt) * 2048 + tid * 4;               \
        cp_async16(sa + tid * 16,          gA);                                \
        cp_async16(sa + tid * 16 + 4096,   gA + 1024);                         \
        cp_async16(sa + 8192 + tid * 16,        gB);                           \
        cp_async16(sa + 8192 + tid * 16 + 4096, gB + 1024);                    \
    } while (0)

    float acc[4][4][4];
#pragma unroll
    for (int i = 0; i < 4; i++)
#pragma unroll
        for (int j = 0; j < 4; j++)
#pragma unroll
            for (int c = 0; c < 4; c++) acc[i][j][c] = 0.f;

    // Prologue: stages 0..2.
    ISSUE(0, 0); CP_COMMIT();
    ISSUE(1, 1); CP_COMMIT();
    ISSUE(2, 2); CP_COMMIT();
    CP_WAIT2();
    __syncthreads();

    for (int kt = 0; kt < NTILES; kt++) {
        // Refill the stage freed at the end of the previous iteration.
        if (kt + 3 < NTILES) ISSUE(kt + 3, (kt + 3) & 3);
        CP_COMMIT();

        const uint32_t* As = smem + (size_t)(kt & 3) * 4096;
        const uint32_t* Bs = As + 2048;

#pragma unroll
        for (int ks = 0; ks < 2; ks++) {
            uint4 av[4];
            uint2 bv[4];
#pragma unroll
            for (int i = 0; i < 4; i++)
                av[i] = *reinterpret_cast<const uint4*>(
                    &As[(((ks << 3) + (wm << 2) + i) << 7) + (lane << 2)]);
#pragma unroll
            for (int j = 0; j < 4; j++)
                bv[j] = *reinterpret_cast<const uint2*>(
                    &Bs[(((ks << 4) + (wn << 2) + j) << 6) + (lane << 1)]);
#pragma unroll
            for (int i = 0; i < 4; i++)
#pragma unroll
                for (int j = 0; j < 4; j++)
                    MMA_TF32(acc[i][j], (reinterpret_cast<uint32_t*>(&av[i])),
                             (reinterpret_cast<uint32_t*>(&bv[j])));
        }

        CP_WAIT2();        // next tile's data resident
        __syncthreads();   // all warps done reading current stage
    }

    // Epilogue.
    float* C = g_qkv + (size_t)blockIdx.y * 128 * QKVC + blockIdx.x * 128;
#pragma unroll
    for (int i = 0; i < 4; i++) {
#pragma unroll
        for (int j = 0; j < 4; j++) {
            int r = wm * 64 + i * 16 + gid;
            int c = wn * 32 + j * 8 + 2 * tig;
            float2 v0 = {acc[i][j][0], acc[i][j][1]};
            float2 v1 = {acc[i][j][2], acc[i][j][3]};
            *reinterpret_cast<float2*>(C + (size_t)(r)     * QKVC + c) = v0;
            *reinterpret_cast<float2*>(C + (size_t)(r + 8) * QKVC + c) = v1;
        }
    }
}

// ---------------------------------------------------------------------------
// Kernel 2: RoPE in-place (q scaled by 1/sqrt(HD)).
// ---------------------------------------------------------------------------
__global__ __launch_bounds__(256) void rope_kernel(const float* __restrict__ cosT,
                                                   const float* __restrict__ sinT) {
    int idx = blockIdx.x * 256 + threadIdx.x;
    int d    = idx & 63;
    int head = (idx >> 6) % 40;
    int t    = idx / (64 * 40);

    float c = cosT[t * HDIM + d];
    float s = sinT[t * HDIM + d];

    float* p = g_qkv + (size_t)t * QKVC + head * HDIM;
    float x1 = p[d];
    float x2 = p[d + 64];
    float o1 = x1 * c - x2 * s;
    float o2 = x2 * c + x1 * s;
    if (head < NH) { o1 *= QSCALE; o2 *= QSCALE; }
    p[d]      = o1;
    p[d + 64] = o2;
}

// ---------------------------------------------------------------------------
// Kernel 3: flash attention (causal, GQA n_rep=4), fp32 (unchanged).
// ---------------------------------------------------------------------------
#define ATTN_SMEM (3 * 64 * 128 * 4 + 64 * 65 * 4)

__global__ __launch_bounds__(256, 1) void attn_kernel(float* __restrict__ out) {
    extern __shared__ float sm[];
    float* Qs = sm;
    float* Ks = sm + 64 * 128;
    float* Vs = sm + 2 * 64 * 128;
    float* Ps = sm + 3 * 64 * 128;

    const int tid = threadIdx.x;
    const int tx = tid & 15;
    const int ty = tid >> 4;
    const int xs = tx & 7;

    const int bh  = blockIdx.y;
    const int b   = bh >> 5;
    const int h   = bh & 31;
    const int kvh = h >> 2;
    const int q0  = blockIdx.x * 64;

    const float* Qg = g_qkv + (size_t)(b * SEQ + q0) * QKVC + h * HDIM;
    const float* Kg = g_qkv + (size_t)(b * SEQ) * QKVC + NH * HDIM + kvh * HDIM;
    const float* Vg = Kg + NKV * HDIM;

#pragma unroll
    for (int i = 0; i < 8; i++) {
        int idx = tid + i * 256;
        int r = idx >> 5;
        int c = (idx & 31) << 2;
        *reinterpret_cast<float4*>(&Qs[r * 128 + c]) =
            *reinterpret_cast<const float4*>(Qg + (size_t)r * QKVC + c);
    }

    float m[4], l[4], o[4][8];
#pragma unroll
    for (int i = 0; i < 4; i++) {
        m[i] = -1e30f; l[i] = 0.f;
#pragma unroll
        for (int j = 0; j < 8; j++) o[i][j] = 0.f;
    }

    const int kb_end = blockIdx.x;
    for (int kb = 0; kb <= kb_end; kb++) {
        __syncthreads();
#pragma unroll
        for (int i = 0; i < 8; i++) {
            int idx = tid + i * 256;
            int r  = idx >> 5;
            int cg = idx & 31;
            float4 kv = *reinterpret_cast<const float4*>(Kg + (size_t)(kb * 64 + r) * QKVC + (cg << 2));
            float4 vv = *reinterpret_cast<const float4*>(Vg + (size_t)(kb * 64 + r) * QKVC + (cg << 2));
            int scg = cg ^ ((r >> 2) & 7);
            *reinterpret_cast<float4*>(&Ks[r * 128 + (scg << 2)]) = kv;
            *reinterpret_cast<float4*>(&Vs[r * 128 + (cg << 2)])  = vv;
        }
        __syncthreads();

        float s4[4][4];
#pragma unroll
        for (int i = 0; i < 4; i++)
#pragma unroll
            for (int j = 0; j < 4; j++) s4[i][j] = 0.f;

#pragma unroll 4
        for (int d = 0; d < 128; d += 4) {
            int scol = (((d >> 2) ^ xs) << 2);
            float4 qv[4], kv[4];
#pragma unroll
            for (int i = 0; i < 4; i++)
                qv[i] = *reinterpret_cast<const float4*>(&Qs[(ty * 4 + i) * 128 + d]);
#pragma unroll
            for (int j = 0; j < 4; j++)
                kv[j] = *reinterpret_cast<const float4*>(&Ks[(tx * 4 + j) * 128 + scol]);
#pragma unroll
            for (int i = 0; i < 4; i++)
#pragma unroll
                for (int j = 0; j < 4; j++) {
                    s4[i][j] = fmaf(qv[i].x, kv[j].x, s4[i][j]);
                    s4[i][j] = fmaf(qv[i].y, kv[j].y, s4[i][j]);
                    s4[i][j] = fmaf(qv[i].z, kv[j].z, s4[i][j]);
                    s4[i][j] = fmaf(qv[i].w, kv[j].w, s4[i][j]);
                }
        }

        if (kb == kb_end) {
#pragma unroll
            for (int i = 0; i < 4; i++)
#pragma unroll
                for (int j = 0; j < 4; j++)
                    if (kb * 64 + tx * 4 + j > q0 + ty * 4 + i) s4[i][j] = -1e30f;
        }

#pragma unroll
        for (int i = 0; i < 4; i++) {
            float rmax = fmaxf(fmaxf(s4[i][0], s4[i][1]), fmaxf(s4[i][2], s4[i][3]));
#pragma unroll
            for (int off = 1; off < 16; off <<= 1)
                rmax = fmaxf(rmax, __shfl_xor_sync(0xffffffffu, rmax, off));
            float nm   = fmaxf(m[i], rmax);
            float corr = __expf(m[i] - nm);
            float rs = 0.f;
#pragma unroll
            for (int j = 0; j < 4; j++) {
                s4[i][j] = __expf(s4[i][j] - nm);
                rs += s4[i][j];
            }
#pragma unroll
            for (int off = 1; off < 16; off <<= 1)
                rs += __shfl_xor_sync(0xffffffffu, rs, off);
            m[i] = nm;
            l[i] = l[i] * corr + rs;
#pragma unroll
            for (int j = 0; j < 8; j++) o[i][j] *= corr;
#pragma unroll
            for (int j = 0; j < 4; j++) Ps[(ty * 4 + i) * 65 + tx * 4 + j] = s4[i][j];
        }
        __syncthreads();

#pragma unroll 4
        for (int k = 0; k < 64; k++) {
            float4 v0 = *reinterpret_cast<const float4*>(&Vs[k * 128 + tx * 8]);
            float4 v1 = *reinterpret_cast<const float4*>(&Vs[k * 128 + tx * 8 + 4]);
#pragma unroll
            for (int i = 0; i < 4; i++) {
                float p = Ps[(ty * 4 + i) * 65 + k];
                o[i][0] = fmaf(p, v0.x, o[i][0]);
                o[i][1] = fmaf(p, v0.y, o[i][1]);
                o[i][2] = fmaf(p, v0.z, o[i][2]);
                o[i][3] = fmaf(p, v0.w, o[i][3]);
                o[i][4] = fmaf(p, v1.x, o[i][4]);
                o[i][5] = fmaf(p, v1.y, o[i][5]);
                o[i][6] = fmaf(p, v1.z, o[i][6]);
                o[i][7] = fmaf(p, v1.w, o[i][7]);
            }
        }
    }

#pragma unroll
    for (int i = 0; i < 4; i++) {
        int t = b * SEQ + q0 + ty * 4 + i;
        float inv = 1.f / l[i];
        float* orow = out + (size_t)t * (NH * HDIM) + h * HDIM + tx * 8;
        float4 v0 = {o[i][0] * inv, o[i][1] * inv, o[i][2] * inv, o[i][3] * inv};
        float4 v1 = {o[i][4] * inv, o[i][5] * inv, o[i][6] * inv, o[i][7] * inv};
        *reinterpret_cast<float4*>(orow)     = v0;
        *reinterpret_cast<float4*>(orow + 4) = v1;
    }
}

// ---------------------------------------------------------------------------
extern "C" void kernel_launch(void* const* d_in, const int* in_sizes, int n_in,
                              void* d_out, int out_size) {
    const float* hidden = (const float*)d_in[0];
    const float* w_qkv  = (const float*)d_in[1];
    const float* cosT   = (const float*)d_in[2];
    const float* sinT   = (const float*)d_in[3];
    float* out = (float*)d_out;

    cudaFuncSetAttribute(gemm_tf32_kernel, cudaFuncAttributeMaxDynamicSharedMemorySize, 65536);
    cudaFuncSetAttribute(attn_kernel, cudaFuncAttributeMaxDynamicSharedMemorySize, ATTN_SMEM);

    // 0) pack + convert (once per launch, memory-bound)
    pack_a_kernel<<<(T_TOK * DMODEL / 4) / 256, 256>>>(hidden);
    pack_w_kernel<<<(DMODEL * QKVC / 4) / 256, 256>>>(w_qkv);

    // 1) GEMM
    dim3 ggrid(QKVC / 128, T_TOK / 128);   // (48, 16)
    gemm_tf32_kernel<<<ggrid, 256, 65536>>>();

    // 2) RoPE
    int rope_threads = T_TOK * (NH + NKV) * 64;
    rope_kernel<<<rope_threads / 256, 256>>>(cosT, sinT);

    // 3) attention
    dim3 agrid(SEQ / 64, NBATCH * NH);     // (16, 64)
    attn_kernel<<<agrid, 256, ATTN_SMEM>>>(out);
}

// round 6
// speedup vs baseline: 3.3858x; 1.5127x over previous
#include <cuda_runtime.h>
#include <cuda_bf16.h>
#include <cstdint>

// Problem constants (B=2, S=1024, H=32, KVH=8, HD=128, DM=4096)
#define T_TOK   2048
#define DMODEL  4096
#define QKVC    6144
#define NH      32
#define NKV     8
#define HDIM    128
#define SEQ     1024
#define NBATCH  2
#define QSCALE  0.08838834764831845f

__device__ float g_qkv[(size_t)T_TOK * QKVC];
__device__ uint32_t g_pa[(size_t)T_TOK * DMODEL];   // packed tf32 A tiles
__device__ uint32_t g_pb[(size_t)QKVC * DMODEL];    // packed tf32 W tiles

__device__ __forceinline__ uint32_t f2tf32(float x) {
    uint32_t u;
    asm("cvt.rna.tf32.f32 %0, %1;" : "=r"(u) : "f"(x));
    return u;
}

#define MMA_TF32(d, a, b)                                                     \
    asm volatile(                                                             \
        "mma.sync.aligned.m16n8k8.row.col.f32.tf32.tf32.f32 "                 \
        "{%0,%1,%2,%3},{%4,%5,%6,%7},{%8,%9},{%0,%1,%2,%3};"                  \
        : "+f"(d[0]), "+f"(d[1]), "+f"(d[2]), "+f"(d[3])                      \
        : "r"(a[0]), "r"(a[1]), "r"(a[2]), "r"(a[3]), "r"(b[0]), "r"(b[1]))

__device__ __forceinline__ void cp_async16(uint32_t smem_addr, const void* gptr) {
    asm volatile("cp.async.cg.shared.global [%0], [%1], 16;"
                 :: "r"(smem_addr), "l"(gptr) : "memory");
}
#define CP_COMMIT() asm volatile("cp.async.commit_group;" ::: "memory")
#define CP_WAIT2()  asm volatile("cp.async.wait_group 2;" ::: "memory")

// ---------------------------------------------------------------------------
// Kernel 0a: pack A [2048,4096] fp32 -> g_pa tf32 fragment-major tiles.
// ---------------------------------------------------------------------------
__global__ __launch_bounds__(256) void pack_a_kernel(const float* __restrict__ A) {
    int i = blockIdx.x * 256 + threadIdx.x;
    int r  = i >> 10;
    int k0 = (i & 1023) << 2;
    float4 v = *reinterpret_cast<const float4*>(A + (size_t)r * DMODEL + k0);

    int mTile = r >> 7, rLoc = r & 127;
    int kTile = k0 >> 4, kLoc = k0 & 15;
    uint32_t* dst = g_pa + ((size_t)(mTile * (DMODEL / 16) + kTile)) * 2048;

    int ks  = kLoc >> 3;
    int kc0 = kLoc & 7;
    int rb  = rLoc >> 4, r16 = rLoc & 15;
    int reg = ((kc0 >= 4) ? 2 : 0) + ((r16 >= 8) ? 1 : 0);
    int base = ((ks << 3) + rb) << 7;
    int lane0 = (r16 & 7) << 2;
    float a[4] = {v.x, v.y, v.z, v.w};
#pragma unroll
    for (int j = 0; j < 4; j++)
        dst[base + ((lane0 + j) << 2) + reg] = f2tf32(a[j]);
}

// ---------------------------------------------------------------------------
// Kernel 0b: pack W [4096,6144] fp32 -> g_pb tf32 fragment-major tiles.
// ---------------------------------------------------------------------------
__global__ __launch_bounds__(256) void pack_w_kernel(const float* __restrict__ W) {
    int i = blockIdx.x * 256 + threadIdx.x;
    int k  = i / 1536;
    int n0 = (i - k * 1536) << 2;
    float4 v = *reinterpret_cast<const float4*>(W + (size_t)k * QKVC + n0);

    int nTile = n0 >> 7, nLoc0 = n0 & 127;
    int kTile = k >> 4,  kLoc  = k & 15;
    uint32_t* dst = g_pb + ((size_t)(nTile * (DMODEL / 16) + kTile)) * 2048;

    int ks = kLoc >> 3, kc = kLoc & 7;
    int kl = kc & 3, rg = kc >> 2;
    float a[4] = {v.x, v.y, v.z, v.w};
#pragma unroll
    for (int j = 0; j < 4; j++) {
        int n = nLoc0 + j;
        int nblk = n >> 3, nn = n & 7;
        dst[((ks << 4) + nblk) * 64 + (((nn << 2) + kl) << 1) + rg] = f2tf32(a[j]);
    }
}

// ---------------------------------------------------------------------------
// Kernel 1: QKV GEMM (unchanged from R5 best).
// ---------------------------------------------------------------------------
__global__ __launch_bounds__(256, 2) void gemm_tf32_kernel() {
    extern __shared__ __align__(16) uint32_t smem[];

    const int tid  = threadIdx.x;
    const int wid  = tid >> 5;
    const int lane = tid & 31;
    const int gid  = lane >> 2;
    const int tig  = lane & 3;
    const int wm   = wid >> 2;
    const int wn   = wid & 3;

    const uint32_t smem_base = (uint32_t)__cvta_generic_to_shared(smem);
    const uint32_t* pa = g_pa + (size_t)blockIdx.y * (DMODEL / 16) * 2048;
    const uint32_t* pb = g_pb + (size_t)blockIdx.x * (DMODEL / 16) * 2048;

    const int NTILES = DMODEL / 16;

#define ISSUE(kt, s)                                                           \
    do {                                                                       \
        uint32_t sa = smem_base + (uint32_t)(s) * 16384;                       \
        const uint32_t* gA = pa + (size_t)(kt) * 2048 + tid * 4;               \
        const uint32_t* gB = pb + (size_t)(kt) * 2048 + tid * 4;               \
        cp_async16(sa + tid * 16,          gA);                                \
        cp_async16(sa + tid * 16 + 4096,   gA + 1024);                         \
        cp_async16(sa + 8192 + tid * 16,        gB);                           \
        cp_async16(sa + 8192 + tid * 16 + 4096, gB + 1024);                    \
    } while (0)

    float acc[4][4][4];
#pragma unroll
    for (int i = 0; i < 4; i++)
#pragma unroll
        for (int j = 0; j < 4; j++)
#pragma unroll
            for (int c = 0; c < 4; c++) acc[i][j][c] = 0.f;

    ISSUE(0, 0); CP_COMMIT();
    ISSUE(1, 1); CP_COMMIT();
    ISSUE(2, 2); CP_COMMIT();
    CP_WAIT2();
    __syncthreads();

    for (int kt = 0; kt < NTILES; kt++) {
        if (kt + 3 < NTILES) ISSUE(kt + 3, (kt + 3) & 3);
        CP_COMMIT();

        const uint32_t* As = smem + (size_t)(kt & 3) * 4096;
        const uint32_t* Bs = As + 2048;

#pragma unroll
        for (int ks = 0; ks < 2; ks++) {
            uint4 av[4];
            uint2 bv[4];
#pragma unroll
            for (int i = 0; i < 4; i++)
                av[i] = *reinterpret_cast<const uint4*>(
                    &As[(((ks << 3) + (wm << 2) + i) << 7) + (lane << 2)]);
#pragma unroll
            for (int j = 0; j < 4; j++)
                bv[j] = *reinterpret_cast<const uint2*>(
                    &Bs[(((ks << 4) + (wn << 2) + j) << 6) + (lane << 1)]);
#pragma unroll
            for (int i = 0; i < 4; i++)
#pragma unroll
                for (int j = 0; j < 4; j++)
                    MMA_TF32(acc[i][j], (reinterpret_cast<uint32_t*>(&av[i])),
                             (reinterpret_cast<uint32_t*>(&bv[j])));
        }

        CP_WAIT2();
        __syncthreads();
    }

    float* C = g_qkv + (size_t)blockIdx.y * 128 * QKVC + blockIdx.x * 128;
#pragma unroll
    for (int i = 0; i < 4; i++) {
#pragma unroll
        for (int j = 0; j < 4; j++) {
            int r = wm * 64 + i * 16 + gid;
            int c = wn * 32 + j * 8 + 2 * tig;
            float2 v0 = {acc[i][j][0], acc[i][j][1]};
            float2 v1 = {acc[i][j][2], acc[i][j][3]};
            *reinterpret_cast<float2*>(C + (size_t)(r)     * QKVC + c) = v0;
            *reinterpret_cast<float2*>(C + (size_t)(r + 8) * QKVC + c) = v1;
        }
    }
}

// ---------------------------------------------------------------------------
// Kernel 2: RoPE in-place (q scaled by 1/sqrt(HD)).
// ---------------------------------------------------------------------------
__global__ __launch_bounds__(256) void rope_kernel(const float* __restrict__ cosT,
                                                   const float* __restrict__ sinT) {
    int idx = blockIdx.x * 256 + threadIdx.x;
    int d    = idx & 63;
    int head = (idx >> 6) % 40;
    int t    = idx / (64 * 40);

    float c = cosT[t * HDIM + d];
    float s = sinT[t * HDIM + d];

    float* p = g_qkv + (size_t)t * QKVC + head * HDIM;
    float x1 = p[d];
    float x2 = p[d + 64];
    float o1 = x1 * c - x2 * s;
    float o2 = x2 * c + x1 * s;
    if (head < NH) { o1 *= QSCALE; o2 *= QSCALE; }
    p[d]      = o1;
    p[d + 64] = o2;
}

// ---------------------------------------------------------------------------
// Kernel 3: tensor-core flash attention (causal, GQA n_rep=4), tf32 mma.
// CTA: 128 queries x 1 head, 256 threads (8 warps), warp owns 16 rows.
// KV tile = 64. Frag layouts match the verified GEMM conventions.
// smem strides: Qs/Ks 132, Vs 136, Ps 68 -> all frag LDS conflict-free.
// ---------------------------------------------------------------------------
#define QS_STR 132
#define KS_STR 132
#define VS_STR 136
#define PS_STR 68
#define QS_WORDS (128 * QS_STR)           // 16896
#define KS_WORDS (64 * KS_STR)            // 8448
#define VS_WORDS (64 * VS_STR)            // 8704
#define PS_WORDS (128 * PS_STR)           // 8704
#define ATTN_SMEM ((QS_WORDS + KS_WORDS + VS_WORDS + PS_WORDS) * 4)  // 171008

__global__ __launch_bounds__(256, 1) void attn_tc_kernel(float* __restrict__ out) {
    extern __shared__ __align__(16) uint32_t sm[];
    uint32_t* Qs = sm;
    uint32_t* Ks = Qs + QS_WORDS;
    uint32_t* Vs = Ks + KS_WORDS;
    uint32_t* Ps = Vs + VS_WORDS;

    const int tid  = threadIdx.x;
    const int wid  = tid >> 5;
    const int lane = tid & 31;
    const int gid  = lane >> 2;
    const int tig  = lane & 3;
    const int qrow = wid * 16;            // warp's local query-row base

    const int b   = blockIdx.y >> 5;
    const int h   = blockIdx.y & 31;
    const int kvh = h >> 2;
    const int q0  = blockIdx.x * 128;

    const float* Qg = g_qkv + (size_t)(b * SEQ + q0) * QKVC + h * HDIM;
    const float* Kg = g_qkv + (size_t)(b * SEQ) * QKVC + NH * HDIM + kvh * HDIM;
    const float* Vg = Kg + NKV * HDIM;

    // Load Q tile 128x128, convert to tf32.
#pragma unroll
    for (int i = 0; i < 16; i++) {
        int idx = tid + i * 256;
        int r = idx >> 5;
        int c = (idx & 31) << 2;
        float4 v = *reinterpret_cast<const float4*>(Qg + (size_t)r * QKVC + c);
        uint32_t* d = &Qs[r * QS_STR + c];
        d[0] = f2tf32(v.x); d[1] = f2tf32(v.y); d[2] = f2tf32(v.z); d[3] = f2tf32(v.w);
    }

    float m[2] = {-1e30f, -1e30f}, l[2] = {0.f, 0.f};
    float oacc[16][4];
#pragma unroll
    for (int nb = 0; nb < 16; nb++)
#pragma unroll
        for (int c = 0; c < 4; c++) oacc[nb][c] = 0.f;

    const int ktiles = 2 * (blockIdx.x + 1);
    for (int kt = 0; kt < ktiles; kt++) {
        const int kv0 = kt * 64;
        __syncthreads();
        // Load K,V tile 64x128 each, convert to tf32.
#pragma unroll
        for (int i = 0; i < 8; i++) {
            int idx = tid + i * 256;
            int r = idx >> 5;
            int c = (idx & 31) << 2;
            float4 kv = *reinterpret_cast<const float4*>(Kg + (size_t)(kv0 + r) * QKVC + c);
            float4 vv = *reinterpret_cast<const float4*>(Vg + (size_t)(kv0 + r) * QKVC + c);
            uint32_t* dk = &Ks[r * KS_STR + c];
            dk[0] = f2tf32(kv.x); dk[1] = f2tf32(kv.y); dk[2] = f2tf32(kv.z); dk[3] = f2tf32(kv.w);
            uint32_t* dv = &Vs[r * VS_STR + c];
            dv[0] = f2tf32(vv.x); dv[1] = f2tf32(vv.y); dv[2] = f2tf32(vv.z); dv[3] = f2tf32(vv.w);
        }
        __syncthreads();

        // ---- S = Q K^T (per warp: 16 x 64) ----
        float sacc[8][4];
#pragma unroll
        for (int nb = 0; nb < 8; nb++)
#pragma unroll
            for (int c = 0; c < 4; c++) sacc[nb][c] = 0.f;

#pragma unroll
        for (int ks = 0; ks < 16; ks++) {
            const int k0 = ks * 8;
            uint32_t a[4];
            a[0] = Qs[(qrow + gid)     * QS_STR + k0 + tig];
            a[1] = Qs[(qrow + gid + 8) * QS_STR + k0 + tig];
            a[2] = Qs[(qrow + gid)     * QS_STR + k0 + tig + 4];
            a[3] = Qs[(qrow + gid + 8) * QS_STR + k0 + tig + 4];
#pragma unroll
            for (int nb = 0; nb < 8; nb++) {
                uint32_t bb[2];
                bb[0] = Ks[(nb * 8 + gid) * KS_STR + k0 + tig];
                bb[1] = Ks[(nb * 8 + gid) * KS_STR + k0 + tig + 4];
                MMA_TF32(sacc[nb], a, bb);
            }
        }

        // Causal mask (only when this tile can cross the diagonal for this warp).
        const int row0 = q0 + qrow + gid;
        const int row1 = row0 + 8;
        if (kv0 + 63 > row0) {
#pragma unroll
            for (int nb = 0; nb < 8; nb++) {
                int c0 = kv0 + nb * 8 + 2 * tig;
                if (c0 > row0)     sacc[nb][0] = -1e30f;
                if (c0 + 1 > row0) sacc[nb][1] = -1e30f;
                if (c0 > row1)     sacc[nb][2] = -1e30f;
                if (c0 + 1 > row1) sacc[nb][3] = -1e30f;
            }
        }

        // ---- online softmax (rows warp-private; quad reduction over tig) ----
#pragma unroll
        for (int r = 0; r < 2; r++) {
            float rmax = -1e30f;
#pragma unroll
            for (int nb = 0; nb < 8; nb++)
                rmax = fmaxf(rmax, fmaxf(sacc[nb][2 * r], sacc[nb][2 * r + 1]));
            rmax = fmaxf(rmax, __shfl_xor_sync(0xffffffffu, rmax, 1));
            rmax = fmaxf(rmax, __shfl_xor_sync(0xffffffffu, rmax, 2));
            float nm = fmaxf(m[r], rmax);
            float corr = __expf(m[r] - nm);
            float rs = 0.f;
#pragma unroll
            for (int nb = 0; nb < 8; nb++) {
                float p0 = __expf(sacc[nb][2 * r]     - nm);
                float p1 = __expf(sacc[nb][2 * r + 1] - nm);
                sacc[nb][2 * r] = p0; sacc[nb][2 * r + 1] = p1;
                rs += p0 + p1;
            }
            rs += __shfl_xor_sync(0xffffffffu, rs, 1);
            rs += __shfl_xor_sync(0xffffffffu, rs, 2);
            m[r] = nm;
            l[r] = l[r] * corr + rs;
#pragma unroll
            for (int nb = 0; nb < 16; nb++) {
                oacc[nb][2 * r]     *= corr;
                oacc[nb][2 * r + 1] *= corr;
            }
        }

        // Store P (tf32) to warp-private Ps rows; no sync needed.
#pragma unroll
        for (int nb = 0; nb < 8; nb++) {
            int c = nb * 8 + 2 * tig;
            Ps[(qrow + gid)     * PS_STR + c]     = f2tf32(sacc[nb][0]);
            Ps[(qrow + gid)     * PS_STR + c + 1] = f2tf32(sacc[nb][1]);
            Ps[(qrow + gid + 8) * PS_STR + c]     = f2tf32(sacc[nb][2]);
            Ps[(qrow + gid + 8) * PS_STR + c + 1] = f2tf32(sacc[nb][3]);
        }

        // ---- O += P V (per warp: 16 x 128) ----
#pragma unroll
        for (int kb = 0; kb < 8; kb++) {
            const int k0 = kb * 8;
            uint32_t a[4];
            a[0] = Ps[(qrow + gid)     * PS_STR + k0 + tig];
            a[1] = Ps[(qrow + gid + 8) * PS_STR + k0 + tig];
            a[2] = Ps[(qrow + gid)     * PS_STR + k0 + tig + 4];
            a[3] = Ps[(qrow + gid + 8) * PS_STR + k0 + tig + 4];
#pragma unroll
            for (int nb = 0; nb < 16; nb++) {
                uint32_t bb[2];
                bb[0] = Vs[(k0 + tig)     * VS_STR + nb * 8 + gid];
                bb[1] = Vs[(k0 + tig + 4) * VS_STR + nb * 8 + gid];
                MMA_TF32(oacc[nb], a, bb);
            }
        }
    }

    // Epilogue: normalize and write.
    const float inv0 = 1.f / l[0];
    const float inv1 = 1.f / l[1];
    const int t0 = b * SEQ + q0 + qrow + gid;
#pragma unroll
    for (int nb = 0; nb < 16; nb++) {
        int c = nb * 8 + 2 * tig;
        float2 v0 = {oacc[nb][0] * inv0, oacc[nb][1] * inv0};
        float2 v1 = {oacc[nb][2] * inv1, oacc[nb][3] * inv1};
        *reinterpret_cast<float2*>(out + (size_t)t0 * (NH * HDIM) + h * HDIM + c) = v0;
        *reinterpret_cast<float2*>(out + (size_t)(t0 + 8) * (NH * HDIM) + h * HDIM + c) = v1;
    }
}

// ---------------------------------------------------------------------------
extern "C" void kernel_launch(void* const* d_in, const int* in_sizes, int n_in,
                              void* d_out, int out_size) {
    const float* hidden = (const float*)d_in[0];
    const float* w_qkv  = (const float*)d_in[1];
    const float* cosT   = (const float*)d_in[2];
    const float* sinT   = (const float*)d_in[3];
    float* out = (float*)d_out;

    cudaFuncSetAttribute(gemm_tf32_kernel, cudaFuncAttributeMaxDynamicSharedMemorySize, 65536);
    cudaFuncSetAttribute(attn_tc_kernel, cudaFuncAttributeMaxDynamicSharedMemorySize, ATTN_SMEM);

    pack_a_kernel<<<(T_TOK * DMODEL / 4) / 256, 256>>>(hidden);
    pack_w_kernel<<<(DMODEL * QKVC / 4) / 256, 256>>>(w_qkv);

    dim3 ggrid(QKVC / 128, T_TOK / 128);
    gemm_tf32_kernel<<<ggrid, 256, 65536>>>();

    int rope_threads = T_TOK * (NH + NKV) * 64;
    rope_kernel<<<rope_threads / 256, 256>>>(cosT, sinT);

    dim3 agrid(SEQ / 128, NBATCH * NH);   // (8, 64)
    attn_tc_kernel<<<agrid, 256, ATTN_SMEM>>>(out);
}